// round 17
// baseline (speedup 1.0000x reference)
#include <cuda_runtime.h>
#include <cuda_bf16.h>

// Device-global scratch (no allocations allowed).
__device__ float    g_P[25 * 112];     // 25 CTA partials: 100 matrix + 10 bias + pad
__device__ float    g_M3[100];         // final composed matrix [out][in] row-major
__device__ float    g_c3[10];          // final composed bias
__device__ unsigned g_ctr1;            // partial arrivals from CTAs 1..24
__device__ unsigned g_flag;            // fold complete
__device__ unsigned g_done;            // CTA-done counter (reset logic)

#define TPB 256
#define NFOLD 25                             // fold CTAs (200 warps, 5 layers each)
#define NSTAGE 3
#define STAGE_PAIRS 240                      // 8 warps x 30 pairs
#define STAGE_FLOATS (STAGE_PAIRS * 20)      // 19200 B
#define STAGE0_F 128                         // stages start 512B in
#define SMEM_BYTES ((STAGE0_F + NSTAGE * STAGE_FLOATS) * 4)   // 58112B -> 3 CTAs/SM

// ---------------------------------------------------------------------------
// PTX helpers.
// ---------------------------------------------------------------------------
__device__ __forceinline__ unsigned smem_u32(const void* p) {
    unsigned r;
    asm("{ .reg .u64 t; cvta.to.shared.u64 t, %1; cvt.u32.u64 %0, t; }"
        : "=r"(r) : "l"(p));
    return r;
}
__device__ __forceinline__ void mbar_init(unsigned addr, unsigned count) {
    asm volatile("mbarrier.init.shared.b64 [%0], %1;" :: "r"(addr), "r"(count) : "memory");
}
__device__ __forceinline__ void mbar_expect_tx(unsigned addr, unsigned bytes) {
    asm volatile("mbarrier.arrive.expect_tx.shared.b64 _, [%0], %1;"
                 :: "r"(addr), "r"(bytes) : "memory");
}
__device__ __forceinline__ void bulk_load(unsigned dst_smem, const void* src_gmem,
                                          unsigned bytes, unsigned mbar) {
    asm volatile("cp.async.bulk.shared::cta.global.mbarrier::complete_tx::bytes "
                 "[%0], [%1], %2, [%3];"
                 :: "r"(dst_smem), "l"(src_gmem), "r"(bytes), "r"(mbar) : "memory");
}
__device__ __forceinline__ void mbar_wait(unsigned addr, unsigned parity) {
    unsigned done;
    asm volatile("{\n\t.reg .pred p;\n\t"
                 "mbarrier.try_wait.parity.acquire.cta.shared::cta.b64 p, [%1], %2;\n\t"
                 "selp.b32 %0, 1, 0, p;\n\t}"
                 : "=r"(done) : "r"(addr), "r"(parity) : "memory");
    while (!done) {
        asm volatile("{\n\t.reg .pred p;\n\t"
                     "mbarrier.try_wait.parity.acquire.cta.shared::cta.b64 p, [%1], %2, 0x989680;\n\t"
                     "selp.b32 %0, 1, 0, p;\n\t}"
                     : "=r"(done) : "r"(addr), "r"(parity) : "memory");
    }
}

// ---------------------------------------------------------------------------
// Fold primitives. Partial layout: 112 floats = [0,100) matrix row-major,
// [100,110) bias, 2 pad. Lane j<10 carries column j; lane 10 carries the bias.
// ---------------------------------------------------------------------------
__device__ __forceinline__ void apply_step(const float* __restrict__ B,
                                           const float* __restrict__ bbias,
                                           int lane, float m[10]) {
    const float2* Br = (const float2*)B;
    float acc[10];
    #pragma unroll
    for (int i = 0; i < 10; ++i) {
        const float2 w0 = Br[i * 5 + 0];
        const float2 w1 = Br[i * 5 + 1];
        const float2 w2 = Br[i * 5 + 2];
        const float2 w3 = Br[i * 5 + 3];
        const float2 w4 = Br[i * 5 + 4];
        float a;
        a = w0.x * m[0];
        a = fmaf(w0.y, m[1], a);
        a = fmaf(w1.x, m[2], a);
        a = fmaf(w1.y, m[3], a);
        a = fmaf(w2.x, m[4], a);
        a = fmaf(w2.y, m[5], a);
        a = fmaf(w3.x, m[6], a);
        a = fmaf(w3.y, m[7], a);
        a = fmaf(w4.x, m[8], a);
        a = fmaf(w4.y, m[9], a);
        acc[i] = a;
    }
    if (lane == 10) {
        #pragma unroll
        for (int i = 0; i < 10; ++i) acc[i] += bbias[i];
    }
    #pragma unroll
    for (int i = 0; i < 10; ++i) m[i] = acc[i];
}

__device__ __forceinline__ void warp_fold_chain(const float* __restrict__ Wsm,
                                                const float* __restrict__ bsm,
                                                int n, int lane, float m[10]) {
    #pragma unroll
    for (int k = 0; k < 10; ++k)
        m[k] = (lane < 10) ? Wsm[k * 10 + lane] : bsm[k];
    #pragma unroll 1
    for (int s = 1; s < n; ++s)
        apply_step(Wsm + s * 100, bsm + s * 10, lane, m);
}

__device__ __forceinline__ void warp_fold2(const float* __restrict__ A,
                                           const float* __restrict__ B,
                                           int lane, float m[10]) {
    #pragma unroll
    for (int k = 0; k < 10; ++k)
        m[k] = (lane < 10) ? A[k * 10 + lane] : A[100 + k];
    apply_step(B, B + 100, lane, m);
}

__device__ __forceinline__ void store_partial(float* __restrict__ D,
                                              const float m[10], int lane) {
    if (lane < 10) {
        #pragma unroll
        for (int k = 0; k < 10; ++k) D[k * 10 + lane] = m[k];
    } else if (lane == 10) {
        #pragma unroll
        for (int k = 0; k < 10; ++k) D[100 + k] = m[k];
    }
}

__device__ __forceinline__ void warp_copy4(float* dst, const float* src,
                                           int nfloats, int lane) {
    const float4* s4 = (const float4*)src;
    float4* d4 = (float4*)dst;
    #pragma unroll 4
    for (int i = lane; i < nfloats / 4; i += 32) d4[i] = s4[i];
}
__device__ __forceinline__ void warp_copy1(float* dst, const float* src,
                                           int nfloats, int lane) {
    for (int i = lane; i < nfloats; i += 32) dst[i] = src[i];
}

__device__ __forceinline__ void issue_tile(float* SH, unsigned bar_s, int s,
                                           long long tile, long long pairs,
                                           const float* x) {
    const long long pbase = tile * STAGE_PAIRS;
    const long long rem = pairs - pbase;
    const unsigned np = (unsigned)(rem < STAGE_PAIRS ? rem : STAGE_PAIRS);
    mbar_expect_tx(bar_s, np * 80u);
    bulk_load(smem_u32(&SH[STAGE0_F + s * STAGE_FLOATS]), x + pbase * 20, np * 80u, bar_s);
}

// ---------------------------------------------------------------------------
// ONE fused kernel (grid = 444 = 3 CTAs/SM, wave-1):
//  - CTAs >= 25: full TMA prologue at t=0.
//  - CTAs 0..24: depth-13 fold (level1: 5 layers/warp; intra-CTA pairwise
//    8->4->2->1; CTA0 pairwise-reduces 25 partials) -> g_M3/g_c3, sets flag;
//    then issue their prologue (stage smem doubled as fold scratch).
//  - All: wait flag, then static-tiled TMA-pipelined apply (R16-proven
//    plain-fmaf loop, 24 warps/SM).
// ---------------------------------------------------------------------------
__global__ void __launch_bounds__(TPB, 3) fused_kernel(const float* __restrict__ Ws,
                                                       const float* __restrict__ bs,
                                                       const float* __restrict__ x,
                                                       float* __restrict__ out,
                                                       long long pairs,
                                                       long long rows) {
    extern __shared__ float SH[];
    const int tid  = threadIdx.x;
    const int cta  = blockIdx.x;
    const int lane = tid & 31;
    const int warp = tid >> 5;

    unsigned bar[NSTAGE];
    #pragma unroll
    for (int s = 0; s < NSTAGE; ++s) bar[s] = smem_u32(&SH[s * 2]);
    if (tid == 0) {
        #pragma unroll
        for (int s = 0; s < NSTAGE; ++s) mbar_init(bar[s], 1);
    }
    __syncthreads();

    const long long tiles   = (pairs + STAGE_PAIRS - 1) / STAGE_PAIRS;
    const long long gstride = gridDim.x;

    if (cta >= NFOLD) {
        // ---- Non-fold CTAs: full prologue immediately ----
        if (tid == 0) {
            #pragma unroll
            for (int s = 0; s < NSTAGE; ++s) {
                const long long t = cta + (long long)s * gstride;
                if (t < tiles) issue_tile(SH, bar[s], s, t, pairs, x);
            }
        }
    } else {
        // ---- Level 1: warp folds chunk = cta*8+warp (5 layers) ----
        const int chunk = cta * 8 + warp;                  // 0..199
        float* slot = SH + STAGE0_F + warp * 560;          // 500 W + 50 b + pad
        float* PA   = SH + STAGE0_F + 8 * 560;             // 8 x 112
        float* PB   = PA + 8 * 112;                        // 4 x 112

        warp_copy4(slot,       Ws + (size_t)chunk * 500, 500, lane);
        warp_copy1(slot + 500, bs + (size_t)chunk * 50,  50,  lane);
        __syncwarp();
        float m[10];
        warp_fold_chain(slot, slot + 500, 5, lane, m);
        store_partial(PA + warp * 112, m, lane);
        __syncthreads();

        // ---- Intra-CTA pairwise: 8 -> 4 -> 2 -> 1 ----
        if (warp < 4) {
            warp_fold2(PA + (2 * warp) * 112, PA + (2 * warp + 1) * 112, lane, m);
            store_partial(PB + warp * 112, m, lane);
        }
        __syncthreads();
        if (warp < 2) {
            warp_fold2(PB + (2 * warp) * 112, PB + (2 * warp + 1) * 112, lane, m);
            store_partial(PA + warp * 112, m, lane);
        }
        __syncthreads();
        if (warp == 0) {
            warp_fold2(PA, PA + 112, lane, m);
            store_partial(g_P + cta * 112, m, lane);   // direct global write
        }
        __threadfence();
        __syncthreads();

        if (cta != 0) {
            if (tid == 0) atomicAdd(&g_ctr1, 1u);
        } else {
            // ---- CTA 0: final pairwise reduce of 25 partials ----
            if (tid == 0) {
                while (*(volatile unsigned*)&g_ctr1 < 24u) __nanosleep(32);
            }
            __syncthreads();
            __threadfence();   // acquire

            float* SA = SH + STAGE0_F;          // 25 x 112 = 2800
            float* SB = SA + 2800;              // up to 13 x 112
            for (int i = tid; i < 25 * 112; i += TPB) SA[i] = g_P[i];
            __syncthreads();

            float* src = SA;
            float* dst = SB;
            int cnt = 25;
            while (cnt > 1) {
                const int half = cnt >> 1;
                for (int w = warp; w < half; w += 8) {
                    float mm[10];
                    warp_fold2(src + (2 * w) * 112, src + (2 * w + 1) * 112, lane, mm);
                    store_partial(dst + w * 112, mm, lane);
                }
                __syncthreads();
                if (cnt & 1) {
                    for (int i = tid; i < 112; i += TPB)
                        dst[half * 112 + i] = src[(cnt - 1) * 112 + i];
                    __syncthreads();
                }
                cnt = half + (cnt & 1);
                float* tp = src; src = dst; dst = tp;
            }
            for (int i = tid; i < 100; i += TPB) g_M3[i] = src[i];
            if (tid < 10) g_c3[tid] = src[100 + tid];
            __threadfence();
            __syncthreads();
            if (tid == 0) *(volatile unsigned*)&g_flag = 1u;
        }

        // ---- Fold CTAs: prologue after fold (stage smem now free) ----
        if (tid == 0) {
            #pragma unroll
            for (int s = 0; s < NSTAGE; ++s) {
                const long long t = cta + (long long)s * gstride;
                if (t < tiles) issue_tile(SH, bar[s], s, t, pairs, x);
            }
        }
    }

    // ================= WAIT FOR THE COMPOSED AFFINE =================
    if (tid == 0) {
        while (*(volatile unsigned*)&g_flag == 0u) __nanosleep(32);
    }
    __syncthreads();
    __threadfence();   // acquire

    // Per-lane constants: phase = lane%5 -> 4 consecutive output floats.
    const int phase = lane % 5;
    const int lp    = lane / 5;              // 5-lane group (0..5; 6 inactive)
    const bool active = (lane < 30);
    const int offA = (phase >= 3) ? 10 : 0;  // source row for outputs w=0,1
    const int offB = (phase >= 2) ? 10 : 0;  // source row for outputs w=2,3

    // Per-lane M rows + biases into registers (R16-proven plain-fmaf form).
    float mw[40], cw[4];
    #pragma unroll
    for (int w = 0; w < 4; ++w) {
        const int jw = (4 * phase + w) % 10;
        cw[w] = __ldg(&g_c3[jw]);
        #pragma unroll
        for (int k = 0; k < 10; ++k) mw[w * 10 + k] = __ldg(&g_M3[jw * 10 + k]);
    }

    float4* out4 = (float4*)out;

    // ================= APPLY (static tiles, TMA pipeline, plain fmaf) ========
    long long i = 0;
    #pragma unroll 1
    for (long long t = cta; t < tiles; t += gstride, ++i) {
        const int s = (int)(i % NSTAGE);
        const unsigned parity = (unsigned)((i / NSTAGE) & 1);
        mbar_wait(bar[s], parity);

        const float* st = &SH[STAGE0_F + s * STAGE_FLOATS];
        const long long tb = t * STAGE_PAIRS;

        #pragma unroll
        for (int it = 0; it < 5; ++it) {
            const int p = warp * 30 + it * 6 + lp;
            const long long gp = tb + p;
            if (active && gp < pairs) {
                const float2* rA = (const float2*)(st + p * 20 + offA);
                const float2* rB = (const float2*)(st + p * 20 + offB);
                float o0 = cw[0], o1 = cw[1], o2 = cw[2], o3 = cw[3];
                #pragma unroll
                for (int kk = 0; kk < 5; ++kk) {
                    const float2 a = rA[kk];
                    const float2 b = rB[kk];
                    o0 = fmaf(mw[2 * kk],          a.x, o0);
                    o0 = fmaf(mw[2 * kk + 1],      a.y, o0);
                    o1 = fmaf(mw[10 + 2 * kk],     a.x, o1);
                    o1 = fmaf(mw[10 + 2 * kk + 1], a.y, o1);
                    o2 = fmaf(mw[20 + 2 * kk],     b.x, o2);
                    o2 = fmaf(mw[20 + 2 * kk + 1], b.y, o2);
                    o3 = fmaf(mw[30 + 2 * kk],     b.x, o3);
                    o3 = fmaf(mw[30 + 2 * kk + 1], b.y, o3);
                }
                out4[gp * 5 + phase] = make_float4(o0, o1, o2, o3);
            }
        }

        __syncthreads();   // all warps done reading stage s
        const long long tn = t + (long long)NSTAGE * gstride;
        if (tn < tiles && tid == 0) issue_tile(SH, bar[s], s, tn, pairs, x);
    }

    // Odd-row tail (rows is even here; kept for safety).
    if ((rows & 1LL) && cta == 0 && tid == 0) {
        const long long r = rows - 1;
        const float* xr = x + r * 10;
        float h[10];
        #pragma unroll
        for (int k = 0; k < 10; ++k) h[k] = xr[k];
        float* orow = out + r * 10;
        #pragma unroll
        for (int j = 0; j < 10; ++j) {
            float a = __ldg(&g_c3[j]);
            #pragma unroll
            for (int k = 0; k < 10; ++k) a += h[k] * __ldg(&g_M3[j * 10 + k]);
            orow[j] = a;
        }
    }

    // ================= RESET (replay-safe; last-finishing CTA) ===============
    __syncthreads();
    __threadfence();
    if (tid == 0) {
        const unsigned old = atomicAdd(&g_done, 1u);
        if (old == gridDim.x - 1) {
            g_done = 0;
            g_ctr1 = 0;
            g_flag = 0;
        }
    }
}

extern "C" void kernel_launch(void* const* d_in, const int* in_sizes, int n_in,
                              void* d_out, int out_size) {
    // Identify inputs by element count: x=BATCH*10, Ws=1000*100, bs=1000*10.
    const float* x  = nullptr;
    const float* Ws = nullptr;
    const float* bs = nullptr;
    long long x_elems = 0;
    for (int i = 0; i < n_in; ++i) {
        if (in_sizes[i] == 1000 * 100) {
            Ws = (const float*)d_in[i];
        } else if (in_sizes[i] == 1000 * 10) {
            bs = (const float*)d_in[i];
        } else {
            x = (const float*)d_in[i];
            x_elems = in_sizes[i];
        }
    }
    const long long rows  = x_elems / 10;
    const long long pairs = rows >> 1;

    static int smem_set = 0;
    if (!smem_set) {
        cudaFuncSetAttribute(fused_kernel,
                             cudaFuncAttributeMaxDynamicSharedMemorySize, SMEM_BYTES);
        smem_set = 1;
    }
    // Single graph node: 444 CTAs = 3/SM (58.1KB smem, 84-reg cap) -> wave-1,
    // spin-safe; 24 warps/SM in the apply phase.
    fused_kernel<<<444, TPB, SMEM_BYTES>>>(Ws, bs, x, (float*)d_out, pairs, rows);
}